// round 2
// baseline (speedup 1.0000x reference)
#include <cuda_runtime.h>
#include <math.h>

#define NN 100000
#define EE 1600000
#define CIN 256
#define C1  128
#define C2  64

// ---------------- scratch (static __device__ — no allocation) ----------------
__device__ float g_deg[NN];
__device__ float g_dis[NN];
__device__ int   g_cnt[NN];
__device__ int   g_rs[NN];     // row start
__device__ int   g_fc[NN];     // fill cursor
__device__ int   g_cursor;
__device__ int   g_eflag;      // 1 if edge_index is int64, 0 if int32
__device__ int   g_nz;         // nonzero-odd-word counter for detection
__device__ int   g_csrc[EE];   // CSR src
__device__ float g_cw[EE];     // CSR edge norm weight
__device__ float g_hlin[(size_t)NN * C1];  // reused for layer-2 lin output
__device__ float g_h[(size_t)NN * C1];
__device__ float g_wcat[128 * 128];

// ---------------- dtype detection ----------------
// Interpret the edge_index buffer as int32 words. If the true dtype is int64
// (little-endian, values in [0, 100000)), every odd word is 0. If int32, odd
// words are random node ids. Count nonzero odd words over the first 2*EE words.
__global__ void k_detect(const int* __restrict__ e32) {
    int i = blockIdx.x * blockDim.x + threadIdx.x;
    if (i == 0) g_nz = 0;
    __syncthreads();
    int odd = 2 * i + 1;
    int v = (odd < 2 * EE) ? e32[odd] : 0;
    unsigned ballot = __ballot_sync(0xffffffffu, v != 0);
    if ((threadIdx.x & 31) == 0 && ballot) atomicAdd(&g_nz, __popc(ballot));
}
__global__ void k_setflag() {
    // int64 layout iff no nonzero odd words were found
    g_eflag = (g_nz == 0) ? 1 : 0;
}

__device__ __forceinline__ int load_src(const int* e32, int e) {
    return g_eflag ? e32[2 * e] : e32[e];
}
__device__ __forceinline__ int load_dst(const int* e32, int e) {
    return g_eflag ? e32[2 * (EE + e)] : e32[EE + e];
}

// ---------------- CSR / norm build ----------------
__global__ void k_init() {
    int i = blockIdx.x * blockDim.x + threadIdx.x;
    if (i < NN) { g_deg[i] = 1.0f; g_cnt[i] = 0; }   // deg starts at 1 (self loop)
    if (i == 0) g_cursor = 0;
}

__global__ void k_deg(const int* __restrict__ e32, const float* __restrict__ ew) {
    int e = blockIdx.x * blockDim.x + threadIdx.x;
    if (e >= EE) return;
    int dst = load_dst(e32, e);
    atomicAdd(&g_deg[dst], ew[e]);
    atomicAdd(&g_cnt[dst], 1);
}

// dis = rsqrt(deg); assign row starts via warp-aggregated cursor atomics
// (order of rows in the CSR pool is irrelevant for a sum).
__global__ void k_prep() {
    int i = blockIdx.x * blockDim.x + threadIdx.x;
    int lane = threadIdx.x & 31;
    int cnt = (i < NN) ? g_cnt[i] : 0;
    int incl = cnt;
#pragma unroll
    for (int off = 1; off < 32; off <<= 1) {
        int v = __shfl_up_sync(0xffffffffu, incl, off);
        if (lane >= off) incl += v;
    }
    int total = __shfl_sync(0xffffffffu, incl, 31);
    int base = 0;
    if (lane == 31) base = atomicAdd(&g_cursor, total);
    base = __shfl_sync(0xffffffffu, base, 31);
    if (i < NN) {
        int start = base + incl - cnt;
        g_rs[i] = start;
        g_fc[i] = start;
        g_dis[i] = rsqrtf(g_deg[i]);   // deg >= 1 always
    }
}

__global__ void k_fill(const int* __restrict__ e32, const float* __restrict__ ew) {
    int e = blockIdx.x * blockDim.x + threadIdx.x;
    if (e >= EE) return;
    int src = load_src(e32, e);
    int dst = load_dst(e32, e);
    float w = g_dis[src] * ew[e] * g_dis[dst];
    int pos = atomicAdd(&g_fc[dst], 1);
    g_csrc[pos] = src;
    g_cw[pos]   = w;
}

// ---------------- fp32 SGEMM: C[M x 128] = A[M x K] @ B[K x 128] ----------------
__global__ __launch_bounds__(256) void k_sgemm(const float* __restrict__ A,
                                               const float* __restrict__ B,
                                               float* __restrict__ C, int M, int K) {
    const int BM = 128, BN = 128, BK = 16, TM = 8, TN = 8;
    __shared__ float As[BK][BM];
    __shared__ float Bs[BK][BN];
    int tid = threadIdx.x;          // 256 threads
    int tx = tid & 15, ty = tid >> 4;
    int row0 = blockIdx.x * BM;
    float acc[TM][TN];
#pragma unroll
    for (int m = 0; m < TM; m++)
#pragma unroll
        for (int n = 0; n < TN; n++) acc[m][n] = 0.f;

    for (int k0 = 0; k0 < K; k0 += BK) {
        // A tile 128x16 (transposed into As[k][m])
#pragma unroll
        for (int i = tid; i < BM * BK / 4; i += 256) {
            int r  = i >> 2;          // row within tile
            int cc = (i & 3) << 2;    // col group
            float4 v = make_float4(0.f, 0.f, 0.f, 0.f);
            int gr = row0 + r;
            if (gr < M) v = *(const float4*)(A + (size_t)gr * K + k0 + cc);
            As[cc + 0][r] = v.x; As[cc + 1][r] = v.y;
            As[cc + 2][r] = v.z; As[cc + 3][r] = v.w;
        }
        // B tile 16x128
#pragma unroll
        for (int i = tid; i < BK * BN / 4; i += 256) {
            int r  = i >> 5;
            int cc = (i & 31) << 2;
            *(float4*)&Bs[r][cc] = *(const float4*)(B + (size_t)(k0 + r) * BN + cc);
        }
        __syncthreads();
#pragma unroll
        for (int k = 0; k < BK; k++) {
            float ar[TM], br[TN];
#pragma unroll
            for (int m = 0; m < TM; m++) ar[m] = As[k][ty * TM + m];
#pragma unroll
            for (int n = 0; n < TN; n++) br[n] = Bs[k][tx * TN + n];
#pragma unroll
            for (int m = 0; m < TM; m++)
#pragma unroll
                for (int n = 0; n < TN; n++) acc[m][n] = fmaf(ar[m], br[n], acc[m][n]);
        }
        __syncthreads();
    }
#pragma unroll
    for (int m = 0; m < TM; m++) {
        int gr = row0 + ty * TM + m;
        if (gr < M) {
            float* cp = C + (size_t)gr * BN + tx * TN;
            *(float4*)cp       = make_float4(acc[m][0], acc[m][1], acc[m][2], acc[m][3]);
            *(float4*)(cp + 4) = make_float4(acc[m][4], acc[m][5], acc[m][6], acc[m][7]);
        }
    }
}

// ---------------- aggregation: out[i] = bias + dis[i]^2*feat[i] + sum_e w*feat[src] ----------------
__global__ void k_agg_relu(const float* __restrict__ feat, const float* __restrict__ bias,
                           float* __restrict__ out) {
    int i = blockIdx.x, c = threadIdx.x;
    float di = g_dis[i];
    float acc = feat[(size_t)i * C1 + c] * (di * di) + bias[c];
    int s = g_rs[i], n = g_cnt[i];
    int e = 0;
    for (; e + 4 <= n; e += 4) {
        int   s0 = g_csrc[s + e],     s1 = g_csrc[s + e + 1];
        int   s2 = g_csrc[s + e + 2], s3 = g_csrc[s + e + 3];
        float w0 = g_cw[s + e],     w1 = g_cw[s + e + 1];
        float w2 = g_cw[s + e + 2], w3 = g_cw[s + e + 3];
        float f0 = feat[(size_t)s0 * C1 + c];
        float f1 = feat[(size_t)s1 * C1 + c];
        float f2 = feat[(size_t)s2 * C1 + c];
        float f3 = feat[(size_t)s3 * C1 + c];
        acc += f0 * w0; acc += f1 * w1; acc += f2 * w2; acc += f3 * w3;
    }
    for (; e < n; e++)
        acc += feat[(size_t)g_csrc[s + e] * C1 + c] * g_cw[s + e];
    out[(size_t)i * C1 + c] = fmaxf(acc, 0.f);
}

__global__ void k_agg_out(const float* __restrict__ feat,
                          const float* __restrict__ bmu, const float* __restrict__ blv,
                          float* __restrict__ omu, float* __restrict__ olv) {
    int i = blockIdx.x, c = threadIdx.x;   // 128 threads: 0-63 mu, 64-127 logvar
    float di = g_dis[i];
    float bias = (c < C2) ? bmu[c] : blv[c - C2];
    float acc = feat[(size_t)i * C1 + c] * (di * di) + bias;
    int s = g_rs[i], n = g_cnt[i];
    int e = 0;
    for (; e + 4 <= n; e += 4) {
        int   s0 = g_csrc[s + e],     s1 = g_csrc[s + e + 1];
        int   s2 = g_csrc[s + e + 2], s3 = g_csrc[s + e + 3];
        float w0 = g_cw[s + e],     w1 = g_cw[s + e + 1];
        float w2 = g_cw[s + e + 2], w3 = g_cw[s + e + 3];
        float f0 = feat[(size_t)s0 * C1 + c];
        float f1 = feat[(size_t)s1 * C1 + c];
        float f2 = feat[(size_t)s2 * C1 + c];
        float f3 = feat[(size_t)s3 * C1 + c];
        acc += f0 * w0; acc += f1 * w1; acc += f2 * w2; acc += f3 * w3;
    }
    for (; e < n; e++)
        acc += feat[(size_t)g_csrc[s + e] * C1 + c] * g_cw[s + e];
    if (c < C2) omu[(size_t)i * C2 + c]        = acc;
    else        olv[(size_t)i * C2 + (c - C2)] = acc;
}

// concatenated weight [128 x 128]: cols 0-63 = Wmu, 64-127 = Wlv
__global__ void k_wcat(const float* __restrict__ Wmu, const float* __restrict__ Wlv) {
    int t = blockIdx.x * blockDim.x + threadIdx.x;
    if (t >= 128 * 128) return;
    int k = t >> 7, c = t & 127;
    g_wcat[t] = (c < C2) ? Wmu[k * C2 + c] : Wlv[k * C2 + (c - C2)];
}

// ---------------- launch ----------------
extern "C" void kernel_launch(void* const* d_in, const int* in_sizes, int n_in,
                              void* d_out, int out_size) {
    const float* x   = (const float*)d_in[0];
    const int*   e32 = (const int*)d_in[1];   // int32 view; true dtype detected on device
    const float* ew  = (const float*)d_in[2];
    const float* W1  = (const float*)d_in[3];
    const float* b1  = (const float*)d_in[4];
    const float* Wmu = (const float*)d_in[5];
    const float* bmu = (const float*)d_in[6];
    const float* Wlv = (const float*)d_in[7];
    const float* blv = (const float*)d_in[8];
    float* out = (float*)d_out;

    void* p;
    cudaGetSymbolAddress(&p, g_hlin); float* hlin = (float*)p;
    cudaGetSymbolAddress(&p, g_h);    float* h    = (float*)p;
    cudaGetSymbolAddress(&p, g_wcat); float* wcat = (float*)p;

    k_detect<<<(EE + 255) / 256, 256>>>(e32);
    k_setflag<<<1, 1>>>();

    k_init<<<(NN + 255) / 256, 256>>>();
    k_deg <<<(EE + 255) / 256, 256>>>(e32, ew);
    k_prep<<<(NN + 255) / 256, 256>>>();
    k_fill<<<(EE + 255) / 256, 256>>>(e32, ew);

    // layer 1: h = relu(S (x @ W1) + b1)
    k_sgemm<<<(NN + 127) / 128, 256>>>(x, W1, hlin, NN, CIN);
    k_agg_relu<<<NN, C1>>>(hlin, b1, h);

    // layer 2+3 fused: ml = h @ [Wmu|Wlv]; [mu|lv] = S ml + [bmu|blv]
    k_wcat<<<64, 256>>>(Wmu, Wlv);
    k_sgemm<<<(NN + 127) / 128, 256>>>(h, wcat, hlin, NN, C1);
    k_agg_out<<<NN, C1>>>(hlin, bmu, blv, out, out + (size_t)NN * C2);
}

// round 3
// speedup vs baseline: 1.2818x; 1.2818x over previous
#include <cuda_runtime.h>
#include <math.h>

#define NN 100000
#define EE 1600000
#define CIN 256
#define C1  128
#define C2  64

// ---------------- scratch (static __device__ — no allocation) ----------------
__device__ float g_deg[NN];
__device__ float g_dis[NN];
__device__ int   g_cnt[NN];
__device__ int   g_rs[NN];     // row start
__device__ int   g_fc[NN];     // fill cursor
__device__ int   g_cursor;
__device__ int   g_eflag;      // 1 if edge_index is int64, 0 if int32
__device__ int   g_csrc[EE];   // CSR src
__device__ float g_cw[EE];     // CSR edge norm weight
__device__ float g_hlin[(size_t)NN * C1];  // reused for layer-2 lin output
__device__ float g_h[(size_t)NN * C1];
__device__ float g_wcat[128 * 128];

// ---------------- dtype detection (sampled, single block) ----------------
// int64 little-endian node ids < 100000 -> every odd 32-bit word is 0.
// int32 layout -> odd words are uniform node ids; 8192 all-zero is impossible.
__global__ void k_detect(const int* __restrict__ e32) {
    int bad = 0;
    for (int i = threadIdx.x; i < 8192; i += 256)
        if (e32[2 * i + 1] != 0) bad = 1;
    int any = __syncthreads_or(bad);
    if (threadIdx.x == 0) g_eflag = any ? 0 : 1;
}

__device__ __forceinline__ int load_src(const int* e32, int e) {
    return g_eflag ? e32[2 * e] : e32[e];
}
__device__ __forceinline__ int load_dst(const int* e32, int e) {
    return g_eflag ? e32[2 * (EE + e)] : e32[EE + e];
}

// ---------------- CSR / norm build ----------------
__global__ void k_init() {
    int i = blockIdx.x * blockDim.x + threadIdx.x;
    if (i < NN) { g_deg[i] = 1.0f; g_cnt[i] = 0; }   // deg starts at 1 (self loop)
    if (i == 0) g_cursor = 0;
}

__global__ void k_deg(const int* __restrict__ e32, const float* __restrict__ ew) {
    int e = blockIdx.x * blockDim.x + threadIdx.x;
    if (e >= EE) return;
    int dst = load_dst(e32, e);
    atomicAdd(&g_deg[dst], ew[e]);
    atomicAdd(&g_cnt[dst], 1);
}

__global__ void k_prep() {
    int i = blockIdx.x * blockDim.x + threadIdx.x;
    int lane = threadIdx.x & 31;
    int cnt = (i < NN) ? g_cnt[i] : 0;
    int incl = cnt;
#pragma unroll
    for (int off = 1; off < 32; off <<= 1) {
        int v = __shfl_up_sync(0xffffffffu, incl, off);
        if (lane >= off) incl += v;
    }
    int total = __shfl_sync(0xffffffffu, incl, 31);
    int base = 0;
    if (lane == 31) base = atomicAdd(&g_cursor, total);
    base = __shfl_sync(0xffffffffu, base, 31);
    if (i < NN) {
        int start = base + incl - cnt;
        g_rs[i] = start;
        g_fc[i] = start;
        g_dis[i] = rsqrtf(g_deg[i]);
    }
}

__global__ void k_fill(const int* __restrict__ e32, const float* __restrict__ ew) {
    int e = blockIdx.x * blockDim.x + threadIdx.x;
    if (e >= EE) return;
    int src = load_src(e32, e);
    int dst = load_dst(e32, e);
    float w = g_dis[src] * ew[e] * g_dis[dst];
    int pos = atomicAdd(&g_fc[dst], 1);
    g_csrc[pos] = src;
    g_cw[pos]   = w;
}

// ---------------- TF32 tensor-core GEMM: C[M x 128] = A[M x K] @ B[K x 128] ----------------
__device__ __forceinline__ unsigned f2tf(float v) {
    unsigned r;
    asm("cvt.rna.tf32.f32 %0, %1;" : "=r"(r) : "f"(v));
    return r;
}

__global__ __launch_bounds__(256) void k_gemm_tf32(const float* __restrict__ A,
                                                   const float* __restrict__ B,
                                                   float* __restrict__ C, int M, int K) {
    const int BM = 128, BK = 32;
    const int PAD = 4, LDS_ = BK + 0;
    (void)LDS_;
    __shared__ unsigned As[BK][BM + PAD];  // [k][m]
    __shared__ unsigned Bs[BK][128 + PAD]; // [k][n]

    int tid  = threadIdx.x;
    int lane = tid & 31;
    int wid  = tid >> 5;          // 8 warps
    int warp_m = wid & 3;         // 4 along M -> 32 rows each
    int warp_n = wid >> 2;        // 2 along N -> 64 cols each
    int gid = lane >> 2;          // 0..7
    int tig = lane & 3;           // 0..3

    int row0 = blockIdx.x * BM;
    int m_base = warp_m * 32;
    int n_base = warp_n * 64;

    float acc[2][8][4];
#pragma unroll
    for (int mt = 0; mt < 2; mt++)
#pragma unroll
        for (int nt = 0; nt < 8; nt++)
#pragma unroll
            for (int r = 0; r < 4; r++) acc[mt][nt][r] = 0.f;

    for (int k0 = 0; k0 < K; k0 += BK) {
        // A tile: 128 rows x 32 k. 256 threads x 16 floats (4x float4), store transposed.
#pragma unroll
        for (int it = 0; it < 4; it++) {
            int idx = tid + it * 256;            // 0..1023 float4 slots
            int r  = idx >> 3;                   // row in tile (128)
            int kc = (idx & 7) << 2;             // k offset (0..28 step 4)
            int gr = row0 + r;
            float4 v = make_float4(0.f, 0.f, 0.f, 0.f);
            if (gr < M) v = *(const float4*)(A + (size_t)gr * K + k0 + kc);
            As[kc + 0][r] = f2tf(v.x);
            As[kc + 1][r] = f2tf(v.y);
            As[kc + 2][r] = f2tf(v.z);
            As[kc + 3][r] = f2tf(v.w);
        }
        // B tile: 32 k x 128 n. 256 threads x 16 floats.
#pragma unroll
        for (int it = 0; it < 4; it++) {
            int idx = tid + it * 256;
            int r  = idx >> 5;                   // k row (32)
            int cc = (idx & 31) << 2;            // n col group
            float4 v = *(const float4*)(B + (size_t)(k0 + r) * 128 + cc);
            Bs[r][cc + 0] = f2tf(v.x);
            Bs[r][cc + 1] = f2tf(v.y);
            Bs[r][cc + 2] = f2tf(v.z);
            Bs[r][cc + 3] = f2tf(v.w);
        }
        __syncthreads();

#pragma unroll
        for (int kk = 0; kk < BK; kk += 8) {
            unsigned a[2][4];
#pragma unroll
            for (int mt = 0; mt < 2; mt++) {
                int mr = m_base + mt * 16;
                a[mt][0] = As[kk + tig    ][mr + gid];
                a[mt][1] = As[kk + tig    ][mr + gid + 8];
                a[mt][2] = As[kk + tig + 4][mr + gid];
                a[mt][3] = As[kk + tig + 4][mr + gid + 8];
            }
#pragma unroll
            for (int nt = 0; nt < 8; nt++) {
                int nc = n_base + nt * 8;
                unsigned b0 = Bs[kk + tig    ][nc + gid];
                unsigned b1 = Bs[kk + tig + 4][nc + gid];
#pragma unroll
                for (int mt = 0; mt < 2; mt++) {
                    asm volatile(
                        "mma.sync.aligned.m16n8k8.row.col.f32.tf32.tf32.f32 "
                        "{%0,%1,%2,%3}, {%4,%5,%6,%7}, {%8,%9}, {%0,%1,%2,%3};"
                        : "+f"(acc[mt][nt][0]), "+f"(acc[mt][nt][1]),
                          "+f"(acc[mt][nt][2]), "+f"(acc[mt][nt][3])
                        : "r"(a[mt][0]), "r"(a[mt][1]), "r"(a[mt][2]), "r"(a[mt][3]),
                          "r"(b0), "r"(b1));
                }
            }
        }
        __syncthreads();
    }

    // writeback: c0,c1 at (gid, tig*2..+1), c2,c3 at (gid+8, ...)
#pragma unroll
    for (int mt = 0; mt < 2; mt++) {
#pragma unroll
        for (int nt = 0; nt < 8; nt++) {
            int nc = n_base + nt * 8 + tig * 2;
            int r0 = row0 + m_base + mt * 16 + gid;
            if (r0 < M)
                *(float2*)(C + (size_t)r0 * 128 + nc) = make_float2(acc[mt][nt][0], acc[mt][nt][1]);
            int r1 = r0 + 8;
            if (r1 < M)
                *(float2*)(C + (size_t)r1 * 128 + nc) = make_float2(acc[mt][nt][2], acc[mt][nt][3]);
        }
    }
}

// ---------------- aggregation: out[i] = bias + dis[i]^2*feat[i] + sum_e w*feat[src] ----------------
__global__ void k_agg_relu(const float* __restrict__ feat, const float* __restrict__ bias,
                           float* __restrict__ out) {
    int i = blockIdx.x, c = threadIdx.x;
    float di = g_dis[i];
    float acc = feat[(size_t)i * C1 + c] * (di * di) + bias[c];
    int s = g_rs[i], n = g_cnt[i];
    int e = 0;
    for (; e + 4 <= n; e += 4) {
        int   s0 = g_csrc[s + e],     s1 = g_csrc[s + e + 1];
        int   s2 = g_csrc[s + e + 2], s3 = g_csrc[s + e + 3];
        float w0 = g_cw[s + e],     w1 = g_cw[s + e + 1];
        float w2 = g_cw[s + e + 2], w3 = g_cw[s + e + 3];
        float f0 = feat[(size_t)s0 * C1 + c];
        float f1 = feat[(size_t)s1 * C1 + c];
        float f2 = feat[(size_t)s2 * C1 + c];
        float f3 = feat[(size_t)s3 * C1 + c];
        acc += f0 * w0; acc += f1 * w1; acc += f2 * w2; acc += f3 * w3;
    }
    for (; e < n; e++)
        acc += feat[(size_t)g_csrc[s + e] * C1 + c] * g_cw[s + e];
    out[(size_t)i * C1 + c] = fmaxf(acc, 0.f);
}

__global__ void k_agg_out(const float* __restrict__ feat,
                          const float* __restrict__ bmu, const float* __restrict__ blv,
                          float* __restrict__ omu, float* __restrict__ olv) {
    int i = blockIdx.x, c = threadIdx.x;
    float di = g_dis[i];
    float bias = (c < C2) ? bmu[c] : blv[c - C2];
    float acc = feat[(size_t)i * C1 + c] * (di * di) + bias;
    int s = g_rs[i], n = g_cnt[i];
    int e = 0;
    for (; e + 4 <= n; e += 4) {
        int   s0 = g_csrc[s + e],     s1 = g_csrc[s + e + 1];
        int   s2 = g_csrc[s + e + 2], s3 = g_csrc[s + e + 3];
        float w0 = g_cw[s + e],     w1 = g_cw[s + e + 1];
        float w2 = g_cw[s + e + 2], w3 = g_cw[s + e + 3];
        float f0 = feat[(size_t)s0 * C1 + c];
        float f1 = feat[(size_t)s1 * C1 + c];
        float f2 = feat[(size_t)s2 * C1 + c];
        float f3 = feat[(size_t)s3 * C1 + c];
        acc += f0 * w0; acc += f1 * w1; acc += f2 * w2; acc += f3 * w3;
    }
    for (; e < n; e++)
        acc += feat[(size_t)g_csrc[s + e] * C1 + c] * g_cw[s + e];
    if (c < C2) omu[(size_t)i * C2 + c]        = acc;
    else        olv[(size_t)i * C2 + (c - C2)] = acc;
}

__global__ void k_wcat(const float* __restrict__ Wmu, const float* __restrict__ Wlv) {
    int t = blockIdx.x * blockDim.x + threadIdx.x;
    if (t >= 128 * 128) return;
    int k = t >> 7, c = t & 127;
    g_wcat[t] = (c < C2) ? Wmu[k * C2 + c] : Wlv[k * C2 + (c - C2)];
}

// ---------------- launch ----------------
extern "C" void kernel_launch(void* const* d_in, const int* in_sizes, int n_in,
                              void* d_out, int out_size) {
    const float* x   = (const float*)d_in[0];
    const int*   e32 = (const int*)d_in[1];
    const float* ew  = (const float*)d_in[2];
    const float* W1  = (const float*)d_in[3];
    const float* b1  = (const float*)d_in[4];
    const float* Wmu = (const float*)d_in[5];
    const float* bmu = (const float*)d_in[6];
    const float* Wlv = (const float*)d_in[7];
    const float* blv = (const float*)d_in[8];
    float* out = (float*)d_out;

    void* p;
    cudaGetSymbolAddress(&p, g_hlin); float* hlin = (float*)p;
    cudaGetSymbolAddress(&p, g_h);    float* h    = (float*)p;
    cudaGetSymbolAddress(&p, g_wcat); float* wcat = (float*)p;

    k_detect<<<1, 256>>>(e32);
    k_init<<<(NN + 255) / 256, 256>>>();
    k_deg <<<(EE + 255) / 256, 256>>>(e32, ew);
    k_prep<<<(NN + 255) / 256, 256>>>();
    k_fill<<<(EE + 255) / 256, 256>>>(e32, ew);

    // layer 1: h = relu(S (x @ W1) + b1)
    k_gemm_tf32<<<(NN + 127) / 128, 256>>>(x, W1, hlin, NN, CIN);
    k_agg_relu<<<NN, C1>>>(hlin, b1, h);

    // layer 2+3 fused: ml = h @ [Wmu|Wlv]; [mu|lv] = S ml + [bmu|blv]
    k_wcat<<<64, 256>>>(Wmu, Wlv);
    k_gemm_tf32<<<(NN + 127) / 128, 256>>>(h, wcat, hlin, NN, C1);
    k_agg_out<<<NN, C1>>>(hlin, bmu, blv, out, out + (size_t)NN * C2);
}

// round 4
// speedup vs baseline: 1.6727x; 1.3050x over previous
#include <cuda_runtime.h>
#include <cuda_fp16.h>
#include <math.h>

#define NN 100000
#define EE 1600000
#define CIN 256
#define C1  128
#define C2  64

// ---------------- scratch (static __device__ — no allocation) ----------------
__device__ float  g_deg[NN];
__device__ float  g_dis[NN];
__device__ int    g_cnt[NN];
__device__ int    g_rs[NN];
__device__ int    g_fc[NN];
__device__ int    g_cursor;
__device__ int    g_eflag;                   // 1 = int64 edge_index, 0 = int32
__device__ int    g_csrc[EE];
__device__ float  g_cw[EE];
__device__ __half g_linh[(size_t)NN * C1];   // GEMM outputs (layer1 lin / layer2 lin)
__device__ __half g_hh[(size_t)NN * C1];     // relu(h) in half
__device__ float  g_wcat[128 * 128];

// ---------------- dtype detection (sampled, single block) ----------------
__global__ void k_detect(const int* __restrict__ e32) {
    int bad = 0;
    for (int i = threadIdx.x; i < 8192; i += 256)
        if (e32[2 * i + 1] != 0) bad = 1;
    int any = __syncthreads_or(bad);
    if (threadIdx.x == 0) g_eflag = any ? 0 : 1;
}
__device__ __forceinline__ int load_src(const int* e32, int e) {
    return g_eflag ? e32[2 * e] : e32[e];
}
__device__ __forceinline__ int load_dst(const int* e32, int e) {
    return g_eflag ? e32[2 * (EE + e)] : e32[EE + e];
}

// ---------------- CSR / norm build ----------------
__global__ void k_init() {
    int i = blockIdx.x * blockDim.x + threadIdx.x;
    if (i < NN) { g_deg[i] = 1.0f; g_cnt[i] = 0; }
    if (i == 0) g_cursor = 0;
}

__global__ void k_deg(const int* __restrict__ e32, const float* __restrict__ ew) {
    int e = blockIdx.x * blockDim.x + threadIdx.x;
    if (e >= EE) return;
    int dst = load_dst(e32, e);
    atomicAdd(&g_deg[dst], ew[e]);
    atomicAdd(&g_cnt[dst], 1);
}

__global__ void k_prep() {
    int i = blockIdx.x * blockDim.x + threadIdx.x;
    int lane = threadIdx.x & 31;
    int cnt = (i < NN) ? g_cnt[i] : 0;
    int incl = cnt;
#pragma unroll
    for (int off = 1; off < 32; off <<= 1) {
        int v = __shfl_up_sync(0xffffffffu, incl, off);
        if (lane >= off) incl += v;
    }
    int total = __shfl_sync(0xffffffffu, incl, 31);
    int base = 0;
    if (lane == 31) base = atomicAdd(&g_cursor, total);
    base = __shfl_sync(0xffffffffu, base, 31);
    if (i < NN) {
        int start = base + incl - cnt;
        g_rs[i] = start;
        g_fc[i] = start;
        g_dis[i] = rsqrtf(g_deg[i]);
    }
}

__global__ void k_fill(const int* __restrict__ e32, const float* __restrict__ ew) {
    int e = blockIdx.x * blockDim.x + threadIdx.x;
    if (e >= EE) return;
    int src = load_src(e32, e);
    int dst = load_dst(e32, e);
    float w = g_dis[src] * ew[e] * g_dis[dst];
    int pos = atomicAdd(&g_fc[dst], 1);
    g_csrc[pos] = src;
    g_cw[pos]   = w;
}

// ---------------- TF32 tensor-core GEMM: Ch[M x 128] = A[M x K] @ B[K x 128] ----------------
__device__ __forceinline__ unsigned f2tf(float v) {
    unsigned r;
    asm("cvt.rna.tf32.f32 %0, %1;" : "=r"(r) : "f"(v));
    return r;
}

template <typename TA>
__global__ __launch_bounds__(256) void k_gemm_tf32(const TA* __restrict__ A,
                                                   const float* __restrict__ B,
                                                   __half* __restrict__ Ch, int M, int K) {
    const int BM = 128, BK = 32, PAD = 4;
    __shared__ unsigned As[BK][BM + PAD];  // [k][m]
    __shared__ unsigned Bs[BK][128 + PAD]; // [k][n]

    int tid  = threadIdx.x;
    int lane = tid & 31;
    int wid  = tid >> 5;
    int warp_m = wid & 3;
    int warp_n = wid >> 2;
    int gid = lane >> 2;
    int tig = lane & 3;

    int row0 = blockIdx.x * BM;
    int m_base = warp_m * 32;
    int n_base = warp_n * 64;

    float acc[2][8][4];
#pragma unroll
    for (int mt = 0; mt < 2; mt++)
#pragma unroll
        for (int nt = 0; nt < 8; nt++)
#pragma unroll
            for (int r = 0; r < 4; r++) acc[mt][nt][r] = 0.f;

    for (int k0 = 0; k0 < K; k0 += BK) {
        // ---- A tile 128x32, transposed into As[k][m] ----
        if constexpr (sizeof(TA) == 4) {
#pragma unroll
            for (int it = 0; it < 4; it++) {
                int idx = tid + it * 256;
                int r  = idx >> 3;
                int kc = (idx & 7) << 2;
                int gr = row0 + r;
                float4 v = make_float4(0.f, 0.f, 0.f, 0.f);
                if (gr < M) v = *(const float4*)((const float*)A + (size_t)gr * K + k0 + kc);
                As[kc + 0][r] = f2tf(v.x);
                As[kc + 1][r] = f2tf(v.y);
                As[kc + 2][r] = f2tf(v.z);
                As[kc + 3][r] = f2tf(v.w);
            }
        } else {
#pragma unroll
            for (int it = 0; it < 2; it++) {
                int idx = tid + it * 256;         // 0..511
                int r  = idx >> 2;                // row 0..127
                int kc = (idx & 3) << 3;          // 0,8,16,24
                int gr = row0 + r;
                uint4 u = make_uint4(0u, 0u, 0u, 0u);
                if (gr < M) u = *(const uint4*)((const __half*)A + (size_t)gr * K + k0 + kc);
                const __half2* hp = (const __half2*)&u;
#pragma unroll
                for (int j = 0; j < 4; j++) {
                    float2 f = __half22float2(hp[j]);
                    As[kc + 2 * j    ][r] = f2tf(f.x);
                    As[kc + 2 * j + 1][r] = f2tf(f.y);
                }
            }
        }
        // ---- B tile 32x128 ----
#pragma unroll
        for (int it = 0; it < 4; it++) {
            int idx = tid + it * 256;
            int r  = idx >> 5;
            int cc = (idx & 31) << 2;
            float4 v = *(const float4*)(B + (size_t)(k0 + r) * 128 + cc);
            Bs[r][cc + 0] = f2tf(v.x);
            Bs[r][cc + 1] = f2tf(v.y);
            Bs[r][cc + 2] = f2tf(v.z);
            Bs[r][cc + 3] = f2tf(v.w);
        }
        __syncthreads();

#pragma unroll
        for (int kk = 0; kk < BK; kk += 8) {
            unsigned a[2][4];
#pragma unroll
            for (int mt = 0; mt < 2; mt++) {
                int mr = m_base + mt * 16;
                a[mt][0] = As[kk + tig    ][mr + gid];
                a[mt][1] = As[kk + tig    ][mr + gid + 8];
                a[mt][2] = As[kk + tig + 4][mr + gid];
                a[mt][3] = As[kk + tig + 4][mr + gid + 8];
            }
#pragma unroll
            for (int nt = 0; nt < 8; nt++) {
                int nc = n_base + nt * 8;
                unsigned b0 = Bs[kk + tig    ][nc + gid];
                unsigned b1 = Bs[kk + tig + 4][nc + gid];
#pragma unroll
                for (int mt = 0; mt < 2; mt++) {
                    asm volatile(
                        "mma.sync.aligned.m16n8k8.row.col.f32.tf32.tf32.f32 "
                        "{%0,%1,%2,%3}, {%4,%5,%6,%7}, {%8,%9}, {%0,%1,%2,%3};"
                        : "+f"(acc[mt][nt][0]), "+f"(acc[mt][nt][1]),
                          "+f"(acc[mt][nt][2]), "+f"(acc[mt][nt][3])
                        : "r"(a[mt][0]), "r"(a[mt][1]), "r"(a[mt][2]), "r"(a[mt][3]),
                          "r"(b0), "r"(b1));
                }
            }
        }
        __syncthreads();
    }

#pragma unroll
    for (int mt = 0; mt < 2; mt++) {
#pragma unroll
        for (int nt = 0; nt < 8; nt++) {
            int nc = n_base + nt * 8 + tig * 2;
            int r0 = row0 + m_base + mt * 16 + gid;
            if (r0 < M)
                *(__half2*)(Ch + (size_t)r0 * 128 + nc) =
                    __floats2half2_rn(acc[mt][nt][0], acc[mt][nt][1]);
            int r1 = r0 + 8;
            if (r1 < M)
                *(__half2*)(Ch + (size_t)r1 * 128 + nc) =
                    __floats2half2_rn(acc[mt][nt][2], acc[mt][nt][3]);
        }
    }
}

// ---------------- aggregation (half2 gathers, fp32 accum) ----------------
// 2 nodes per 128-thread block; 64 threads x half2 = 128 channels per node.
__global__ __launch_bounds__(128) void k_agg_relu(const __half2* __restrict__ feat,
                                                  const float* __restrict__ bias,
                                                  __half2* __restrict__ out) {
    int node = blockIdx.x * 2 + (threadIdx.x >> 6);
    int c2 = threadIdx.x & 63;
    if (node >= NN) return;
    float di = g_dis[node];
    float2 self = __half22float2(feat[(size_t)node * 64 + c2]);
    float2 acc;
    acc.x = self.x * (di * di) + bias[2 * c2];
    acc.y = self.y * (di * di) + bias[2 * c2 + 1];
    int s = g_rs[node], n = g_cnt[node];
    int e = 0;
    for (; e + 4 <= n; e += 4) {
        int   s0 = g_csrc[s + e],     s1 = g_csrc[s + e + 1];
        int   s2 = g_csrc[s + e + 2], s3 = g_csrc[s + e + 3];
        float w0 = g_cw[s + e],       w1 = g_cw[s + e + 1];
        float w2 = g_cw[s + e + 2],   w3 = g_cw[s + e + 3];
        float2 f0 = __half22float2(feat[(size_t)s0 * 64 + c2]);
        float2 f1 = __half22float2(feat[(size_t)s1 * 64 + c2]);
        float2 f2 = __half22float2(feat[(size_t)s2 * 64 + c2]);
        float2 f3 = __half22float2(feat[(size_t)s3 * 64 + c2]);
        acc.x += f0.x * w0 + f1.x * w1 + f2.x * w2 + f3.x * w3;
        acc.y += f0.y * w0 + f1.y * w1 + f2.y * w2 + f3.y * w3;
    }
    for (; e < n; e++) {
        float w = g_cw[s + e];
        float2 f = __half22float2(feat[(size_t)g_csrc[s + e] * 64 + c2]);
        acc.x += f.x * w; acc.y += f.y * w;
    }
    out[(size_t)node * 64 + c2] = __floats2half2_rn(fmaxf(acc.x, 0.f), fmaxf(acc.y, 0.f));
}

__global__ __launch_bounds__(128) void k_agg_out(const __half2* __restrict__ feat,
                                                 const float* __restrict__ bmu,
                                                 const float* __restrict__ blv,
                                                 float* __restrict__ omu,
                                                 float* __restrict__ olv) {
    int node = blockIdx.x * 2 + (threadIdx.x >> 6);
    int c2 = threadIdx.x & 63;
    if (node >= NN) return;
    float di = g_dis[node];
    float b0, b1;
    if (c2 < 32) { b0 = bmu[2 * c2];        b1 = bmu[2 * c2 + 1]; }
    else         { b0 = blv[2 * (c2 - 32)]; b1 = blv[2 * (c2 - 32) + 1]; }
    float2 self = __half22float2(feat[(size_t)node * 64 + c2]);
    float2 acc;
    acc.x = self.x * (di * di) + b0;
    acc.y = self.y * (di * di) + b1;
    int s = g_rs[node], n = g_cnt[node];
    int e = 0;
    for (; e + 4 <= n; e += 4) {
        int   s0 = g_csrc[s + e],     s1 = g_csrc[s + e + 1];
        int   s2 = g_csrc[s + e + 2], s3 = g_csrc[s + e + 3];
        float w0 = g_cw[s + e],       w1 = g_cw[s + e + 1];
        float w2 = g_cw[s + e + 2],   w3 = g_cw[s + e + 3];
        float2 f0 = __half22float2(feat[(size_t)s0 * 64 + c2]);
        float2 f1 = __half22float2(feat[(size_t)s1 * 64 + c2]);
        float2 f2 = __half22float2(feat[(size_t)s2 * 64 + c2]);
        float2 f3 = __half22float2(feat[(size_t)s3 * 64 + c2]);
        acc.x += f0.x * w0 + f1.x * w1 + f2.x * w2 + f3.x * w3;
        acc.y += f0.y * w0 + f1.y * w1 + f2.y * w2 + f3.y * w3;
    }
    for (; e < n; e++) {
        float w = g_cw[s + e];
        float2 f = __half22float2(feat[(size_t)g_csrc[s + e] * 64 + c2]);
        acc.x += f.x * w; acc.y += f.y * w;
    }
    if (c2 < 32)
        *(float2*)(omu + (size_t)node * 64 + 2 * c2) = acc;
    else
        *(float2*)(olv + (size_t)node * 64 + 2 * (c2 - 32)) = acc;
}

__global__ void k_wcat(const float* __restrict__ Wmu, const float* __restrict__ Wlv) {
    int t = blockIdx.x * blockDim.x + threadIdx.x;
    if (t >= 128 * 128) return;
    int k = t >> 7, c = t & 127;
    g_wcat[t] = (c < C2) ? Wmu[k * C2 + c] : Wlv[k * C2 + (c - C2)];
}

// ---------------- launch ----------------
extern "C" void kernel_launch(void* const* d_in, const int* in_sizes, int n_in,
                              void* d_out, int out_size) {
    const float* x   = (const float*)d_in[0];
    const int*   e32 = (const int*)d_in[1];
    const float* ew  = (const float*)d_in[2];
    const float* W1  = (const float*)d_in[3];
    const float* b1  = (const float*)d_in[4];
    const float* Wmu = (const float*)d_in[5];
    const float* bmu = (const float*)d_in[6];
    const float* Wlv = (const float*)d_in[7];
    const float* blv = (const float*)d_in[8];
    float* out = (float*)d_out;

    void* p;
    cudaGetSymbolAddress(&p, g_linh); __half* linh = (__half*)p;
    cudaGetSymbolAddress(&p, g_hh);   __half* hh   = (__half*)p;
    cudaGetSymbolAddress(&p, g_wcat); float*  wcat = (float*)p;

    k_detect<<<1, 256>>>(e32);
    k_init<<<(NN + 255) / 256, 256>>>();
    k_deg <<<(EE + 255) / 256, 256>>>(e32, ew);
    k_prep<<<(NN + 255) / 256, 256>>>();
    k_fill<<<(EE + 255) / 256, 256>>>(e32, ew);

    // layer 1: h = relu(S (x @ W1) + b1)
    k_gemm_tf32<float><<<(NN + 127) / 128, 256>>>(x, W1, linh, NN, CIN);
    k_agg_relu<<<(NN + 1) / 2, 128>>>((const __half2*)linh, b1, (__half2*)hh);

    // layer 2+3 fused: ml = h @ [Wmu|Wlv]; [mu|lv] = S ml + [bmu|blv]
    k_wcat<<<64, 256>>>(Wmu, Wlv);
    k_gemm_tf32<__half><<<(NN + 127) / 128, 256>>>(hh, wcat, linh, NN, C1);
    k_agg_out<<<(NN + 1) / 2, 128>>>((const __half2*)linh, bmu, blv,
                                     out, out + (size_t)NN * C2);
}

// round 5
// speedup vs baseline: 1.8561x; 1.1096x over previous
#include <cuda_runtime.h>
#include <cuda_fp16.h>
#include <math.h>

#define NN 100000
#define EE 1600000
#define CIN 256
#define C1  128
#define C2  64

// ---------------- scratch (static __device__ — no allocation) ----------------
__device__ float  g_deg[NN];
__device__ float  g_dis[NN];
__device__ int    g_cnt[NN];
__device__ int    g_rs[NN];
__device__ int    g_fc[NN];
__device__ int    g_cursor;
__device__ int    g_eflag;                   // 1 = int64 edge_index, 0 = int32
__device__ int2   g_edata[EE];               // (src, w-as-bits) interleaved
__device__ __half g_linh[(size_t)NN * C1];   // GEMM outputs (layer1 lin / layer2 lin)
__device__ __half g_hh[(size_t)NN * C1];     // relu(h) in half
__device__ float  g_wcat[128 * 128];

// ---------------- dtype detection (sampled, single block) ----------------
__global__ void k_detect(const int* __restrict__ e32) {
    int bad = 0;
    for (int i = threadIdx.x; i < 8192; i += 256)
        if (e32[2 * i + 1] != 0) bad = 1;
    int any = __syncthreads_or(bad);
    if (threadIdx.x == 0) g_eflag = any ? 0 : 1;
}
__device__ __forceinline__ int load_src(const int* e32, int e) {
    return g_eflag ? e32[2 * e] : e32[e];
}
__device__ __forceinline__ int load_dst(const int* e32, int e) {
    return g_eflag ? e32[2 * (EE + e)] : e32[EE + e];
}

// ---------------- CSR / norm build ----------------
__global__ void k_init() {
    int i = blockIdx.x * blockDim.x + threadIdx.x;
    if (i < NN) { g_deg[i] = 1.0f; g_cnt[i] = 0; }
    if (i == 0) g_cursor = 0;
}

__global__ void k_deg(const int* __restrict__ e32, const float* __restrict__ ew) {
    int e = blockIdx.x * blockDim.x + threadIdx.x;
    if (e >= EE) return;
    int dst = load_dst(e32, e);
    atomicAdd(&g_deg[dst], ew[e]);
    atomicAdd(&g_cnt[dst], 1);
}

__global__ void k_prep() {
    int i = blockIdx.x * blockDim.x + threadIdx.x;
    int lane = threadIdx.x & 31;
    int cnt = (i < NN) ? g_cnt[i] : 0;
    int incl = cnt;
#pragma unroll
    for (int off = 1; off < 32; off <<= 1) {
        int v = __shfl_up_sync(0xffffffffu, incl, off);
        if (lane >= off) incl += v;
    }
    int total = __shfl_sync(0xffffffffu, incl, 31);
    int base = 0;
    if (lane == 31) base = atomicAdd(&g_cursor, total);
    base = __shfl_sync(0xffffffffu, base, 31);
    if (i < NN) {
        int start = base + incl - cnt;
        g_rs[i] = start;
        g_fc[i] = start;
        g_dis[i] = rsqrtf(g_deg[i]);
    }
}

__global__ void k_fill(const int* __restrict__ e32, const float* __restrict__ ew) {
    int e = blockIdx.x * blockDim.x + threadIdx.x;
    if (e >= EE) return;
    int src = load_src(e32, e);
    int dst = load_dst(e32, e);
    float w = g_dis[src] * ew[e] * g_dis[dst];
    int pos = atomicAdd(&g_fc[dst], 1);
    g_edata[pos] = make_int2(src, __float_as_int(w));
}

// ---------------- TF32 tensor-core GEMM: Ch[M x 128] = A[M x K] @ B[K x 128] ----------------
__device__ __forceinline__ unsigned f2tf(float v) {
    unsigned r;
    asm("cvt.rna.tf32.f32 %0, %1;" : "=r"(r) : "f"(v));
    return r;
}

template <typename TA>
__global__ __launch_bounds__(256) void k_gemm_tf32(const TA* __restrict__ A,
                                                   const float* __restrict__ B,
                                                   __half* __restrict__ Ch, int M, int K) {
    const int BM = 128, BK = 32, PAD = 4;
    __shared__ unsigned As[BK][BM + PAD];  // [k][m]
    __shared__ unsigned Bs[BK][128 + PAD]; // [k][n]

    int tid  = threadIdx.x;
    int lane = tid & 31;
    int wid  = tid >> 5;
    int warp_m = wid & 3;
    int warp_n = wid >> 2;
    int gid = lane >> 2;
    int tig = lane & 3;

    int row0 = blockIdx.x * BM;
    int m_base = warp_m * 32;
    int n_base = warp_n * 64;

    float acc[2][8][4];
#pragma unroll
    for (int mt = 0; mt < 2; mt++)
#pragma unroll
        for (int nt = 0; nt < 8; nt++)
#pragma unroll
            for (int r = 0; r < 4; r++) acc[mt][nt][r] = 0.f;

    for (int k0 = 0; k0 < K; k0 += BK) {
        if constexpr (sizeof(TA) == 4) {
#pragma unroll
            for (int it = 0; it < 4; it++) {
                int idx = tid + it * 256;
                int r  = idx >> 3;
                int kc = (idx & 7) << 2;
                int gr = row0 + r;
                float4 v = make_float4(0.f, 0.f, 0.f, 0.f);
                if (gr < M) v = *(const float4*)((const float*)A + (size_t)gr * K + k0 + kc);
                As[kc + 0][r] = f2tf(v.x);
                As[kc + 1][r] = f2tf(v.y);
                As[kc + 2][r] = f2tf(v.z);
                As[kc + 3][r] = f2tf(v.w);
            }
        } else {
#pragma unroll
            for (int it = 0; it < 2; it++) {
                int idx = tid + it * 256;
                int r  = idx >> 2;
                int kc = (idx & 3) << 3;
                int gr = row0 + r;
                uint4 u = make_uint4(0u, 0u, 0u, 0u);
                if (gr < M) u = *(const uint4*)((const __half*)A + (size_t)gr * K + k0 + kc);
                const __half2* hp = (const __half2*)&u;
#pragma unroll
                for (int j = 0; j < 4; j++) {
                    float2 f = __half22float2(hp[j]);
                    As[kc + 2 * j    ][r] = f2tf(f.x);
                    As[kc + 2 * j + 1][r] = f2tf(f.y);
                }
            }
        }
#pragma unroll
        for (int it = 0; it < 4; it++) {
            int idx = tid + it * 256;
            int r  = idx >> 5;
            int cc = (idx & 31) << 2;
            float4 v = *(const float4*)(B + (size_t)(k0 + r) * 128 + cc);
            Bs[r][cc + 0] = f2tf(v.x);
            Bs[r][cc + 1] = f2tf(v.y);
            Bs[r][cc + 2] = f2tf(v.z);
            Bs[r][cc + 3] = f2tf(v.w);
        }
        __syncthreads();

#pragma unroll
        for (int kk = 0; kk < BK; kk += 8) {
            unsigned a[2][4];
#pragma unroll
            for (int mt = 0; mt < 2; mt++) {
                int mr = m_base + mt * 16;
                a[mt][0] = As[kk + tig    ][mr + gid];
                a[mt][1] = As[kk + tig    ][mr + gid + 8];
                a[mt][2] = As[kk + tig + 4][mr + gid];
                a[mt][3] = As[kk + tig + 4][mr + gid + 8];
            }
#pragma unroll
            for (int nt = 0; nt < 8; nt++) {
                int nc = n_base + nt * 8;
                unsigned b0 = Bs[kk + tig    ][nc + gid];
                unsigned b1 = Bs[kk + tig + 4][nc + gid];
#pragma unroll
                for (int mt = 0; mt < 2; mt++) {
                    asm volatile(
                        "mma.sync.aligned.m16n8k8.row.col.f32.tf32.tf32.f32 "
                        "{%0,%1,%2,%3}, {%4,%5,%6,%7}, {%8,%9}, {%0,%1,%2,%3};"
                        : "+f"(acc[mt][nt][0]), "+f"(acc[mt][nt][1]),
                          "+f"(acc[mt][nt][2]), "+f"(acc[mt][nt][3])
                        : "r"(a[mt][0]), "r"(a[mt][1]), "r"(a[mt][2]), "r"(a[mt][3]),
                          "r"(b0), "r"(b1));
                }
            }
        }
        __syncthreads();
    }

#pragma unroll
    for (int mt = 0; mt < 2; mt++) {
#pragma unroll
        for (int nt = 0; nt < 8; nt++) {
            int nc = n_base + nt * 8 + tig * 2;
            int r0 = row0 + m_base + mt * 16 + gid;
            if (r0 < M)
                *(__half2*)(Ch + (size_t)r0 * 128 + nc) =
                    __floats2half2_rn(acc[mt][nt][0], acc[mt][nt][1]);
            int r1 = r0 + 8;
            if (r1 < M)
                *(__half2*)(Ch + (size_t)r1 * 128 + nc) =
                    __floats2half2_rn(acc[mt][nt][2], acc[mt][nt][3]);
        }
    }
}

// ---------------- aggregation (half2 gathers, fp32 accum) ----------------
__global__ __launch_bounds__(128) void k_agg_relu(const __half2* __restrict__ feat,
                                                  const float* __restrict__ bias,
                                                  __half2* __restrict__ out) {
    int node = blockIdx.x * 2 + (threadIdx.x >> 6);
    int c2 = threadIdx.x & 63;
    if (node >= NN) return;
    float di = g_dis[node];
    float2 self = __half22float2(feat[(size_t)node * 64 + c2]);
    float2 acc;
    acc.x = self.x * (di * di) + bias[2 * c2];
    acc.y = self.y * (di * di) + bias[2 * c2 + 1];
    int s = g_rs[node], n = g_cnt[node];
    int e = 0;
    for (; e + 4 <= n; e += 4) {
        int2 d0 = g_edata[s + e],     d1 = g_edata[s + e + 1];
        int2 d2 = g_edata[s + e + 2], d3 = g_edata[s + e + 3];
        float2 f0 = __half22float2(feat[(size_t)d0.x * 64 + c2]);
        float2 f1 = __half22float2(feat[(size_t)d1.x * 64 + c2]);
        float2 f2 = __half22float2(feat[(size_t)d2.x * 64 + c2]);
        float2 f3 = __half22float2(feat[(size_t)d3.x * 64 + c2]);
        float w0 = __int_as_float(d0.y), w1 = __int_as_float(d1.y);
        float w2 = __int_as_float(d2.y), w3 = __int_as_float(d3.y);
        acc.x += f0.x * w0 + f1.x * w1 + f2.x * w2 + f3.x * w3;
        acc.y += f0.y * w0 + f1.y * w1 + f2.y * w2 + f3.y * w3;
    }
    for (; e < n; e++) {
        int2 d = g_edata[s + e];
        float w = __int_as_float(d.y);
        float2 f = __half22float2(feat[(size_t)d.x * 64 + c2]);
        acc.x += f.x * w; acc.y += f.y * w;
    }
    out[(size_t)node * 64 + c2] = __floats2half2_rn(fmaxf(acc.x, 0.f), fmaxf(acc.y, 0.f));
}

__global__ __launch_bounds__(128) void k_agg_out(const __half2* __restrict__ feat,
                                                 const float* __restrict__ bmu,
                                                 const float* __restrict__ blv,
                                                 float* __restrict__ omu,
                                                 float* __restrict__ olv) {
    int node = blockIdx.x * 2 + (threadIdx.x >> 6);
    int c2 = threadIdx.x & 63;
    if (node >= NN) return;
    float di = g_dis[node];
    float b0, b1;
    if (c2 < 32) { b0 = bmu[2 * c2];        b1 = bmu[2 * c2 + 1]; }
    else         { b0 = blv[2 * (c2 - 32)]; b1 = blv[2 * (c2 - 32) + 1]; }
    float2 self = __half22float2(feat[(size_t)node * 64 + c2]);
    float2 acc;
    acc.x = self.x * (di * di) + b0;
    acc.y = self.y * (di * di) + b1;
    int s = g_rs[node], n = g_cnt[node];
    int e = 0;
    for (; e + 4 <= n; e += 4) {
        int2 d0 = g_edata[s + e],     d1 = g_edata[s + e + 1];
        int2 d2 = g_edata[s + e + 2], d3 = g_edata[s + e + 3];
        float2 f0 = __half22float2(feat[(size_t)d0.x * 64 + c2]);
        float2 f1 = __half22float2(feat[(size_t)d1.x * 64 + c2]);
        float2 f2 = __half22float2(feat[(size_t)d2.x * 64 + c2]);
        float2 f3 = __half22float2(feat[(size_t)d3.x * 64 + c2]);
        float w0 = __int_as_float(d0.y), w1 = __int_as_float(d1.y);
        float w2 = __int_as_float(d2.y), w3 = __int_as_float(d3.y);
        acc.x += f0.x * w0 + f1.x * w1 + f2.x * w2 + f3.x * w3;
        acc.y += f0.y * w0 + f1.y * w1 + f2.y * w2 + f3.y * w3;
    }
    for (; e < n; e++) {
        int2 d = g_edata[s + e];
        float w = __int_as_float(d.y);
        float2 f = __half22float2(feat[(size_t)d.x * 64 + c2]);
        acc.x += f.x * w; acc.y += f.y * w;
    }
    if (c2 < 32)
        *(float2*)(omu + (size_t)node * 64 + 2 * c2) = acc;
    else
        *(float2*)(olv + (size_t)node * 64 + 2 * (c2 - 32)) = acc;
}

__global__ void k_wcat(const float* __restrict__ Wmu, const float* __restrict__ Wlv) {
    int t = blockIdx.x * blockDim.x + threadIdx.x;
    if (t >= 128 * 128) return;
    int k = t >> 7, c = t & 127;
    g_wcat[t] = (c < C2) ? Wmu[k * C2 + c] : Wlv[k * C2 + (c - C2)];
}

// ---------------- launch ----------------
extern "C" void kernel_launch(void* const* d_in, const int* in_sizes, int n_in,
                              void* d_out, int out_size) {
    const float* x   = (const float*)d_in[0];
    const int*   e32 = (const int*)d_in[1];
    const float* ew  = (const float*)d_in[2];
    const float* W1  = (const float*)d_in[3];
    const float* b1  = (const float*)d_in[4];
    const float* Wmu = (const float*)d_in[5];
    const float* bmu = (const float*)d_in[6];
    const float* Wlv = (const float*)d_in[7];
    const float* blv = (const float*)d_in[8];
    float* out = (float*)d_out;

    void* p;
    cudaGetSymbolAddress(&p, g_linh); __half* linh = (__half*)p;
    cudaGetSymbolAddress(&p, g_hh);   __half* hh   = (__half*)p;
    cudaGetSymbolAddress(&p, g_wcat); float*  wcat = (float*)p;

    // Lazily-created side stream + fork/join events (host handles only;
    // device work per call is identical on every invocation).
    static cudaStream_t s2 = nullptr;
    static cudaEvent_t evF = nullptr, evJ = nullptr;
    if (!s2) {
        cudaStreamCreateWithFlags(&s2, cudaStreamNonBlocking);
        cudaEventCreateWithFlags(&evF, cudaEventDisableTiming);
        cudaEventCreateWithFlags(&evJ, cudaEventDisableTiming);
    }

    // Fork: CSR build chain on side stream, GEMM1 (+wcat) on main stream.
    cudaEventRecord(evF, 0);
    cudaStreamWaitEvent(s2, evF, 0);

    k_detect<<<1, 256, 0, s2>>>(e32);
    k_init<<<(NN + 255) / 256, 256, 0, s2>>>();
    k_deg <<<(EE + 255) / 256, 256, 0, s2>>>(e32, ew);
    k_prep<<<(NN + 255) / 256, 256, 0, s2>>>();
    k_fill<<<(EE + 255) / 256, 256, 0, s2>>>(e32, ew);
    cudaEventRecord(evJ, s2);

    k_wcat<<<64, 256>>>(Wmu, Wlv);
    k_gemm_tf32<float><<<(NN + 127) / 128, 256>>>(x, W1, linh, NN, CIN);

    // Join: everything below needs the CSR.
    cudaStreamWaitEvent(0, evJ, 0);

    // layer 1: h = relu(S (x @ W1) + b1)
    k_agg_relu<<<(NN + 1) / 2, 128>>>((const __half2*)linh, b1, (__half2*)hh);

    // layer 2+3 fused: ml = h @ [Wmu|Wlv]; [mu|lv] = S ml + [bmu|blv]
    k_gemm_tf32<__half><<<(NN + 127) / 128, 256>>>(hh, wcat, linh, NN, C1);
    k_agg_out<<<(NN + 1) / 2, 128>>>((const __half2*)linh, bmu, blv,
                                     out, out + (size_t)NN * C2);
}

// round 7
// speedup vs baseline: 2.0486x; 1.1037x over previous
#include <cuda_runtime.h>
#include <cuda_fp16.h>
#include <math.h>

#define NN 100000
#define EE 1600000
#define CIN 256
#define C1  128
#define C2  64
#define NLO 50000   // layer-1 agg split point (node halves)

// ---------------- scratch (static __device__ — no allocation) ----------------
__device__ float  g_deg[NN];
__device__ float  g_dis[NN];
__device__ int    g_cnt[NN];
__device__ int    g_rs[NN];
__device__ int    g_fc[NN];
__device__ int    g_cursor;
__device__ int    g_eflag;                   // 1 = int64 edge_index, 0 = int32
__device__ int2   g_edata[EE];               // (src, w-as-bits) interleaved
__device__ __half g_linh[(size_t)NN * C1];   // layer-1 GEMM output
__device__ __half g_hh[(size_t)NN * C1];     // relu(h)
__device__ __half g_lin2[(size_t)NN * C1];   // layer-2 GEMM output (disjoint from g_linh!)

// ---------------- dtype detection (sampled, single block) ----------------
__global__ void k_detect(const int* __restrict__ e32) {
    int bad = 0;
    for (int i = threadIdx.x; i < 8192; i += 256)
        if (e32[2 * i + 1] != 0) bad = 1;
    int any = __syncthreads_or(bad);
    if (threadIdx.x == 0) g_eflag = any ? 0 : 1;
}
__device__ __forceinline__ int load_src(const int* e32, int e) {
    return g_eflag ? e32[2 * e] : e32[e];
}
__device__ __forceinline__ int load_dst(const int* e32, int e) {
    return g_eflag ? e32[2 * (EE + e)] : e32[EE + e];
}

// ---------------- CSR / norm build ----------------
__global__ void k_init() {
    int i = blockIdx.x * blockDim.x + threadIdx.x;
    if (i < NN) { g_deg[i] = 1.0f; g_cnt[i] = 0; }
    if (i == 0) g_cursor = 0;
}

__global__ void k_deg(const int* __restrict__ e32, const float* __restrict__ ew) {
    int e = blockIdx.x * blockDim.x + threadIdx.x;
    if (e >= EE) return;
    int dst = load_dst(e32, e);
    atomicAdd(&g_deg[dst], ew[e]);
    atomicAdd(&g_cnt[dst], 1);
}

__global__ void k_prep() {
    int i = blockIdx.x * blockDim.x + threadIdx.x;
    int lane = threadIdx.x & 31;
    int cnt = (i < NN) ? g_cnt[i] : 0;
    int incl = cnt;
#pragma unroll
    for (int off = 1; off < 32; off <<= 1) {
        int v = __shfl_up_sync(0xffffffffu, incl, off);
        if (lane >= off) incl += v;
    }
    int total = __shfl_sync(0xffffffffu, incl, 31);
    int base = 0;
    if (lane == 31) base = atomicAdd(&g_cursor, total);
    base = __shfl_sync(0xffffffffu, base, 31);
    if (i < NN) {
        int start = base + incl - cnt;
        g_rs[i] = start;
        g_fc[i] = start;
        g_dis[i] = rsqrtf(g_deg[i]);
    }
}

__global__ void k_fill(const int* __restrict__ e32, const float* __restrict__ ew) {
    int e = blockIdx.x * blockDim.x + threadIdx.x;
    if (e >= EE) return;
    int src = load_src(e32, e);
    int dst = load_dst(e32, e);
    float w = g_dis[src] * ew[e] * g_dis[dst];
    int pos = atomicAdd(&g_fc[dst], 1);
    g_edata[pos] = make_int2(src, __float_as_int(w));
}

// ---------------- TF32 tensor-core GEMM: Ch[M x 128] = A[M x K] @ B[K x 128] ----------------
__device__ __forceinline__ unsigned f2tf(float v) {
    unsigned r;
    asm("cvt.rna.tf32.f32 %0, %1;" : "=r"(r) : "f"(v));
    return r;
}

template <typename TA, bool SPLITB>
__global__ __launch_bounds__(256) void k_gemm_tf32(const TA* __restrict__ A,
                                                   const float* __restrict__ B1,
                                                   const float* __restrict__ B2,
                                                   __half* __restrict__ Ch, int M, int K) {
    const int BM = 128, BK = 32, PAD = 4;
    __shared__ unsigned As[BK][BM + PAD];  // [k][m]
    __shared__ unsigned Bs[BK][128 + PAD]; // [k][n]

    int tid  = threadIdx.x;
    int lane = tid & 31;
    int wid  = tid >> 5;
    int warp_m = wid & 3;
    int warp_n = wid >> 2;
    int gid = lane >> 2;
    int tig = lane & 3;

    int row0 = blockIdx.x * BM;
    int m_base = warp_m * 32;
    int n_base = warp_n * 64;

    float acc[2][8][4];
#pragma unroll
    for (int mt = 0; mt < 2; mt++)
#pragma unroll
        for (int nt = 0; nt < 8; nt++)
#pragma unroll
            for (int r = 0; r < 4; r++) acc[mt][nt][r] = 0.f;

    for (int k0 = 0; k0 < K; k0 += BK) {
        if constexpr (sizeof(TA) == 4) {
#pragma unroll
            for (int it = 0; it < 4; it++) {
                int idx = tid + it * 256;
                int r  = idx >> 3;
                int kc = (idx & 7) << 2;
                int gr = row0 + r;
                float4 v = make_float4(0.f, 0.f, 0.f, 0.f);
                if (gr < M) v = *(const float4*)((const float*)A + (size_t)gr * K + k0 + kc);
                As[kc + 0][r] = f2tf(v.x);
                As[kc + 1][r] = f2tf(v.y);
                As[kc + 2][r] = f2tf(v.z);
                As[kc + 3][r] = f2tf(v.w);
            }
        } else {
#pragma unroll
            for (int it = 0; it < 2; it++) {
                int idx = tid + it * 256;
                int r  = idx >> 2;
                int kc = (idx & 3) << 3;
                int gr = row0 + r;
                uint4 u = make_uint4(0u, 0u, 0u, 0u);
                if (gr < M) u = *(const uint4*)((const __half*)A + (size_t)gr * K + k0 + kc);
                const __half2* hp = (const __half2*)&u;
#pragma unroll
                for (int j = 0; j < 4; j++) {
                    float2 f = __half22float2(hp[j]);
                    As[kc + 2 * j    ][r] = f2tf(f.x);
                    As[kc + 2 * j + 1][r] = f2tf(f.y);
                }
            }
        }
#pragma unroll
        for (int it = 0; it < 4; it++) {
            int idx = tid + it * 256;
            int r  = idx >> 5;
            int cc = (idx & 31) << 2;
            float4 v;
            if constexpr (SPLITB) {
                v = (cc < 64)
                    ? *(const float4*)(B1 + (size_t)(k0 + r) * 64 + cc)
                    : *(const float4*)(B2 + (size_t)(k0 + r) * 64 + (cc - 64));
            } else {
                v = *(const float4*)(B1 + (size_t)(k0 + r) * 128 + cc);
            }
            Bs[r][cc + 0] = f2tf(v.x);
            Bs[r][cc + 1] = f2tf(v.y);
            Bs[r][cc + 2] = f2tf(v.z);
            Bs[r][cc + 3] = f2tf(v.w);
        }
        __syncthreads();

#pragma unroll
        for (int kk = 0; kk < BK; kk += 8) {
            unsigned a[2][4];
#pragma unroll
            for (int mt = 0; mt < 2; mt++) {
                int mr = m_base + mt * 16;
                a[mt][0] = As[kk + tig    ][mr + gid];
                a[mt][1] = As[kk + tig    ][mr + gid + 8];
                a[mt][2] = As[kk + tig + 4][mr + gid];
                a[mt][3] = As[kk + tig + 4][mr + gid + 8];
            }
#pragma unroll
            for (int nt = 0; nt < 8; nt++) {
                int nc = n_base + nt * 8;
                unsigned b0 = Bs[kk + tig    ][nc + gid];
                unsigned b1 = Bs[kk + tig + 4][nc + gid];
#pragma unroll
                for (int mt = 0; mt < 2; mt++) {
                    asm volatile(
                        "mma.sync.aligned.m16n8k8.row.col.f32.tf32.tf32.f32 "
                        "{%0,%1,%2,%3}, {%4,%5,%6,%7}, {%8,%9}, {%0,%1,%2,%3};"
                        : "+f"(acc[mt][nt][0]), "+f"(acc[mt][nt][1]),
                          "+f"(acc[mt][nt][2]), "+f"(acc[mt][nt][3])
                        : "r"(a[mt][0]), "r"(a[mt][1]), "r"(a[mt][2]), "r"(a[mt][3]),
                          "r"(b0), "r"(b1));
                }
            }
        }
        __syncthreads();
    }

#pragma unroll
    for (int mt = 0; mt < 2; mt++) {
#pragma unroll
        for (int nt = 0; nt < 8; nt++) {
            int nc = n_base + nt * 8 + tig * 2;
            int r0 = row0 + m_base + mt * 16 + gid;
            if (r0 < M)
                *(__half2*)(Ch + (size_t)r0 * 128 + nc) =
                    __floats2half2_rn(acc[mt][nt][0], acc[mt][nt][1]);
            int r1 = r0 + 8;
            if (r1 < M)
                *(__half2*)(Ch + (size_t)r1 * 128 + nc) =
                    __floats2half2_rn(acc[mt][nt][2], acc[mt][nt][3]);
        }
    }
}

// ---------------- aggregation: 1 warp per node, uint2 (4-channel) gathers ----------------
__device__ __forceinline__ float4 up4(uint2 v, float w, float4 acc) {
    float2 a = __half22float2(*(const __half2*)&v.x);
    float2 b = __half22float2(*(const __half2*)&v.y);
    acc.x = fmaf(a.x, w, acc.x); acc.y = fmaf(a.y, w, acc.y);
    acc.z = fmaf(b.x, w, acc.z); acc.w = fmaf(b.y, w, acc.w);
    return acc;
}

__global__ __launch_bounds__(256) void k_agg_relu(const uint2* __restrict__ feat,
                                                  const float* __restrict__ bias,
                                                  uint2* __restrict__ out,
                                                  int node0, int ncount) {
    int warp = threadIdx.x >> 5;
    int lane = threadIdx.x & 31;
    int node = node0 + blockIdx.x * 8 + warp;
    if (node >= node0 + ncount) return;

    float di = g_dis[node];
    float dd = di * di;
    float4 b = *(const float4*)(bias + 4 * lane);
    uint2 sv = feat[(size_t)node * 32 + lane];
    float4 acc = make_float4(b.x, b.y, b.z, b.w);
    acc = up4(sv, dd, acc);

    int s = g_rs[node], n = g_cnt[node];
    int e = 0;
    for (; e + 4 <= n; e += 4) {
        int2 d0 = g_edata[s + e],     d1 = g_edata[s + e + 1];
        int2 d2 = g_edata[s + e + 2], d3 = g_edata[s + e + 3];
        uint2 f0 = feat[(size_t)d0.x * 32 + lane];
        uint2 f1 = feat[(size_t)d1.x * 32 + lane];
        uint2 f2 = feat[(size_t)d2.x * 32 + lane];
        uint2 f3 = feat[(size_t)d3.x * 32 + lane];
        acc = up4(f0, __int_as_float(d0.y), acc);
        acc = up4(f1, __int_as_float(d1.y), acc);
        acc = up4(f2, __int_as_float(d2.y), acc);
        acc = up4(f3, __int_as_float(d3.y), acc);
    }
    for (; e < n; e++) {
        int2 d = g_edata[s + e];
        uint2 f = feat[(size_t)d.x * 32 + lane];
        acc = up4(f, __int_as_float(d.y), acc);
    }
    __half2 h0 = __floats2half2_rn(fmaxf(acc.x, 0.f), fmaxf(acc.y, 0.f));
    __half2 h1 = __floats2half2_rn(fmaxf(acc.z, 0.f), fmaxf(acc.w, 0.f));
    uint2 o;
    o.x = *(const unsigned*)&h0;
    o.y = *(const unsigned*)&h1;
    out[(size_t)node * 32 + lane] = o;
}

__global__ __launch_bounds__(256) void k_agg_out(const uint2* __restrict__ feat,
                                                 const float* __restrict__ bmu,
                                                 const float* __restrict__ blv,
                                                 float* __restrict__ omu,
                                                 float* __restrict__ olv) {
    int warp = threadIdx.x >> 5;
    int lane = threadIdx.x & 31;
    int node = blockIdx.x * 8 + warp;
    if (node >= NN) return;

    float di = g_dis[node];
    float dd = di * di;
    float4 b = (lane < 16) ? *(const float4*)(bmu + 4 * lane)
                           : *(const float4*)(blv + 4 * (lane - 16));
    uint2 sv = feat[(size_t)node * 32 + lane];
    float4 acc = make_float4(b.x, b.y, b.z, b.w);
    acc = up4(sv, dd, acc);

    int s = g_rs[node], n = g_cnt[node];
    int e = 0;
    for (; e + 4 <= n; e += 4) {
        int2 d0 = g_edata[s + e],     d1 = g_edata[s + e + 1];
        int2 d2 = g_edata[s + e + 2], d3 = g_edata[s + e + 3];
        uint2 f0 = feat[(size_t)d0.x * 32 + lane];
        uint2 f1 = feat[(size_t)d1.x * 32 + lane];
        uint2 f2 = feat[(size_t)d2.x * 32 + lane];
        uint2 f3 = feat[(size_t)d3.x * 32 + lane];
        acc = up4(f0, __int_as_float(d0.y), acc);
        acc = up4(f1, __int_as_float(d1.y), acc);
        acc = up4(f2, __int_as_float(d2.y), acc);
        acc = up4(f3, __int_as_float(d3.y), acc);
    }
    for (; e < n; e++) {
        int2 d = g_edata[s + e];
        uint2 f = feat[(size_t)d.x * 32 + lane];
        acc = up4(f, __int_as_float(d.y), acc);
    }
    if (lane < 16)
        *(float4*)(omu + (size_t)node * 64 + 4 * lane) = acc;
    else
        *(float4*)(olv + (size_t)node * 64 + 4 * (lane - 16)) = acc;
}

// ---------------- launch ----------------
extern "C" void kernel_launch(void* const* d_in, const int* in_sizes, int n_in,
                              void* d_out, int out_size) {
    const float* x   = (const float*)d_in[0];
    const int*   e32 = (const int*)d_in[1];
    const float* ew  = (const float*)d_in[2];
    const float* W1  = (const float*)d_in[3];
    const float* b1  = (const float*)d_in[4];
    const float* Wmu = (const float*)d_in[5];
    const float* bmu = (const float*)d_in[6];
    const float* Wlv = (const float*)d_in[7];
    const float* blv = (const float*)d_in[8];
    float* out = (float*)d_out;

    void* p;
    cudaGetSymbolAddress(&p, g_linh); __half* linh = (__half*)p;
    cudaGetSymbolAddress(&p, g_hh);   __half* hh   = (__half*)p;
    cudaGetSymbolAddress(&p, g_lin2); __half* lin2 = (__half*)p;

    static cudaStream_t s2 = nullptr;
    static cudaEvent_t evF = nullptr, evJ = nullptr, evA = nullptr, evB = nullptr;
    if (!s2) {
        cudaStreamCreateWithFlags(&s2, cudaStreamNonBlocking);
        cudaEventCreateWithFlags(&evF, cudaEventDisableTiming);
        cudaEventCreateWithFlags(&evJ, cudaEventDisableTiming);
        cudaEventCreateWithFlags(&evA, cudaEventDisableTiming);
        cudaEventCreateWithFlags(&evB, cudaEventDisableTiming);
    }

    // Fork: CSR build on side stream, GEMM1 on main stream.
    cudaEventRecord(evF, 0);
    cudaStreamWaitEvent(s2, evF, 0);

    k_detect<<<1, 256, 0, s2>>>(e32);
    k_init<<<(NN + 255) / 256, 256, 0, s2>>>();
    k_deg <<<(EE + 255) / 256, 256, 0, s2>>>(e32, ew);
    k_prep<<<(NN + 255) / 256, 256, 0, s2>>>();
    k_fill<<<(EE + 255) / 256, 256, 0, s2>>>(e32, ew);
    cudaEventRecord(evJ, s2);

    k_gemm_tf32<float, false><<<(NN + 127) / 128, 256>>>(x, W1, nullptr, linh, NN, CIN);

    // Join: aggregation needs CSR.
    cudaStreamWaitEvent(0, evJ, 0);

    // layer 1 agg, lower half (nodes [0, NLO))
    k_agg_relu<<<(NLO + 7) / 8, 256>>>((const uint2*)linh, b1, (uint2*)hh, 0, NLO);
    cudaEventRecord(evA, 0);

    // upper half on side stream, concurrent with GEMM2_lo.
    // GEMM2 writes lin2 (disjoint from linh) so this read of linh is race-free.
    cudaStreamWaitEvent(s2, evA, 0);
    k_agg_relu<<<(NN - NLO + 7) / 8, 256, 0, s2>>>((const uint2*)linh, b1, (uint2*)hh, NLO, NN - NLO);
    cudaEventRecord(evB, s2);

    // GEMM2 lower half (rows [0, NLO)) — only needs hh[0..NLO)
    k_gemm_tf32<__half, true><<<(NLO + 127) / 128, 256>>>(hh, Wmu, Wlv, lin2, NLO, C1);

    // join upper-half agg, then GEMM2 upper half
    cudaStreamWaitEvent(0, evB, 0);
    k_gemm_tf32<__half, true><<<(NN - NLO + 127) / 128, 256>>>(
        hh + (size_t)NLO * C1, Wmu, Wlv, lin2 + (size_t)NLO * C1, NN - NLO, C1);

    // final aggregation -> mu | logvar
    k_agg_out<<<(NN + 7) / 8, 256>>>((const uint2*)lin2, bmu, blv,
                                     out, out + (size_t)NN * C2);
}